// round 10
// baseline (speedup 1.0000x reference)
#include <cuda_runtime.h>
#include <cuda_fp16.h>
#include <cstdint>

// CapsuleLayer dynamic routing, 3 rounds.
// x: [512, 1152, 8] fp32   W: [10, 1152, 8, 16] fp32   out: [10, 512, 16] fp32
//
// Block = (n, 6 batches) -- BT=6 amortizes the W stream (the only per-block
// L1 term that doesn't scale with batches) over 50% more output.
// Pre-pass: repack W into caps_Wq2 (fp32, bitwise identical):
//   Wq2[n][g][i][rq][oq] (float4) = W[n][g*8+rq][i][4*oq..4*oq+3]
//   -> phase-1 warp instr i reads 512B contiguous (4 wf/LDG.128, L1 floor).
// Phase 1: warp = row-octet; lane = (rq 0..7, oq 0..3); batches in 3
//   register-bounded pairs. Priors -> fp16 smem, PSTR=16, 16B-chunk XOR
//   swizzle (chunk q at q ^ ((r>>2)&1)): conflict-free STS.64 and LDS.64.
// Phase 2: 6 groups x 128 threads, 9 rows/thread, streamed LDS.64 rows
//   (R8-proven form), max-free softmax (shift-invariant, |a|<~20): one fused
//   a/e/Z/S pass per round. v0 = squash(mean p). w = v0, then v0+v1.
// 512 = 86*6-4: x reads clamped, output stores guarded (phantom batches
// replicate b=511; finite, no overflow risk).

#define NCAPS 10
#define NB    512
#define NR    1152
#define CI    8
#define CO    16
#define BT    6
#define NTHREADS 768
#define GROUPS 86                 // ceil(512/6)
#define TPB   128                 // threads per batch group (4 warps)
#define WPG   4
#define KPT   (NR / TPB)          // 9 rows per thread in routing
#define NWARP (NTHREADS / 32)     // 24
#define OCT   (NR / 8)            // 144 row-octets
#define JIT   (OCT / NWARP)       // 6 octets per warp
#define PSTR  16                  // halves per prior row (exact, swizzled)

// shared memory layout (bytes)
#define P_BYTES    (BT * NR * PSTR * 2)   // 221184 fp16 priors
#define SRED_OFF   P_BYTES
#define SRED_BYTES (BT * WPG * CO * 4)    // 1536
#define WRED_OFF   (SRED_OFF + SRED_BYTES)
#define WRED_BYTES (BT * WPG * 4)         // 96
#define VDOT_OFF   (WRED_OFF + WRED_BYTES)
#define VDOT_BYTES (BT * CO * 4)          // 384
#define SMEM_TOTAL (VDOT_OFF + VDOT_BYTES) // 223200

// repacked W: [NCAPS][OCT][CI][8 rq][4 oq] float4
__device__ __align__(16) float caps_Wq2[NCAPS * NR * CI * CO];

struct __align__(8) H4 { __half2 a, b; };
typedef unsigned long long u64;

__device__ __forceinline__ void fma2(u64& d, u64 a, u64 b) {
    asm("fma.rn.f32x2 %0, %1, %2, %0;" : "+l"(d) : "l"(a), "l"(b));
}
__device__ __forceinline__ u64 pack2(float x) {
    u64 r; asm("mov.b64 %0, {%1, %1};" : "=l"(r) : "f"(x)); return r;
}
__device__ __forceinline__ u64 packf2(float x, float y) {
    u64 r; asm("mov.b64 %0, {%1, %2};" : "=l"(r) : "f"(x), "f"(y)); return r;
}
__device__ __forceinline__ float2 unpack2(u64 v) {
    float2 f; asm("mov.b64 {%0, %1}, %2;" : "=f"(f.x), "=f"(f.y) : "l"(v));
    return f;
}
__device__ __forceinline__ void bar_group(int id) {
    asm volatile("bar.sync %0, %1;" :: "r"(id), "r"(TPB) : "memory");
}

// Load logical row r (16B-chunk swizzled, LDS.64 granularity) into f[16].
__device__ __forceinline__ void load_row_sw(const __half* pb, int r,
                                            float f[CO]) {
    const uint2* base = (const uint2*)(pb + (size_t)r * PSTR);
    const int d = ((r >> 2) & 1) << 1;     // chunk swizzle in uint2 units
    #pragma unroll
    for (int h = 0; h < 4; ++h) {
        const uint2 u = base[h ^ d];       // swaps pairs of uint2 = 16B chunks
        const float2 f0 = __half22float2(*(const __half2*)&u.x);
        const float2 f1 = __half22float2(*(const __half2*)&u.y);
        f[h*4+0] = f0.x; f[h*4+1] = f0.y; f[h*4+2] = f1.x; f[h*4+3] = f1.y;
    }
}

// Split-exchange reduce of S[16] over 32 lanes: 16 shfl total.
__device__ __forceinline__ void reduce_s16(float S[CO], int lane,
                                           float* sred_warp) {
    const bool h16 = lane & 16;
    #pragma unroll
    for (int j = 0; j < 8; ++j) {
        const float snd = h16 ? S[j] : S[j + 8];
        const float kp  = h16 ? S[j + 8] : S[j];
        S[j] = kp + __shfl_xor_sync(0xffffffffu, snd, 16);
    }
    const bool h8 = lane & 8;
    #pragma unroll
    for (int j = 0; j < 4; ++j) {
        const float snd = h8 ? S[j] : S[j + 4];
        const float kp  = h8 ? S[j + 4] : S[j];
        S[j] = kp + __shfl_xor_sync(0xffffffffu, snd, 8);
    }
    const bool h4 = lane & 4;
    #pragma unroll
    for (int j = 0; j < 2; ++j) {
        const float snd = h4 ? S[j] : S[j + 2];
        const float kp  = h4 ? S[j + 2] : S[j];
        S[j] = kp + __shfl_xor_sync(0xffffffffu, snd, 4);
    }
    const bool h2 = lane & 2;
    {
        const float snd = h2 ? S[0] : S[1];
        const float kp  = h2 ? S[1] : S[0];
        S[0] = kp + __shfl_xor_sync(0xffffffffu, snd, 2);
    }
    S[0] += __shfl_xor_sync(0xffffffffu, S[0], 1);
    const int comp = ((lane >> 4) & 1) * 8 + ((lane >> 3) & 1) * 4 +
                     ((lane >> 2) & 1) * 2 + ((lane >> 1) & 1);
    if (!(lane & 1)) sred_warp[comp] = S[0];
}

// ---------- W repack: one thread per output float4 ----------
__global__ void __launch_bounds__(256)
repack_kernel(const float* __restrict__ W) {
    const int idx = blockIdx.x * blockDim.x + threadIdx.x;
    if (idx >= NCAPS * OCT * CI * 32) return;
    const int oq = idx & 3;
    const int rq = (idx >> 2) & 7;
    const int i  = (idx >> 5) & 7;
    const int rb = idx >> 8;               // n*OCT + g
    const float4* src = (const float4*)W + ((size_t)(rb * 8 + rq) * 8 + i) * 4 + oq;
    ((float4*)caps_Wq2)[idx] = *src;
}

__global__ void __launch_bounds__(NTHREADS, 1)
caps_kernel(const float* __restrict__ x,
            float* __restrict__ out) {
    extern __shared__ char smem[];
    __half* p   = (__half*)smem;
    float* sred = (float*)(smem + SRED_OFF);
    float* wred = (float*)(smem + WRED_OFF);
    float* vdot = (float*)(smem + VDOT_OFF);

    const int n  = blockIdx.y;
    const int b0 = blockIdx.x * BT;
    const int t  = threadIdx.x;
    const int wid  = t >> 5;
    const int lane = t & 31;

    // ======== Phase 1: priors GEMM (octet mapping) ========
    // lane = (rq 0..7, oq 0..3)
    {
        const int rq = lane >> 2;
        const int oq = lane & 3;
        const int q  = oq >> 1;            // 16B chunk this lane's H4 lives in
        const int sub = (oq & 1) << 2;     // half-offset within chunk (halves)
        #pragma unroll 1
        for (int j = 0; j < JIT; ++j) {
            const int g = wid + j * NWARP;
            const int r = g * 8 + rq;
            const int s = (r >> 2) & 1;
            const int choff = ((q ^ s) << 3) + sub;   // halves within row
            const float4* wq =
                (const float4*)caps_Wq2 + ((size_t)(n * OCT + g) * 8) * 32
                + rq * 4 + oq;
            float4 wc[CI];
            #pragma unroll
            for (int i = 0; i < CI; ++i) wc[i] = wq[i * 32];

            // batches in 3 pairs keeps live registers ~70
            #pragma unroll
            for (int bp = 0; bp < 3; ++bp) {
                float xv[2][CI];
                #pragma unroll
                for (int bb = 0; bb < 2; ++bb) {
                    const int gb0 = b0 + bp * 2 + bb;
                    const int gb  = gb0 < NB ? gb0 : (NB - 1);   // clamp
                    const float4* xp =
                        (const float4*)(x + ((size_t)gb * NR + r) * CI);
                    const float4 x0 = xp[0], x1 = xp[1];
                    xv[bb][0]=x0.x; xv[bb][1]=x0.y; xv[bb][2]=x0.z; xv[bb][3]=x0.w;
                    xv[bb][4]=x1.x; xv[bb][5]=x1.y; xv[bb][6]=x1.z; xv[bb][7]=x1.w;
                }
                u64 acc[2][2];
                acc[0][0]=0ull; acc[0][1]=0ull; acc[1][0]=0ull; acc[1][1]=0ull;
                #pragma unroll
                for (int i = 0; i < CI; ++i) {
                    const u64 wlo = packf2(wc[i].x, wc[i].y);
                    const u64 whi = packf2(wc[i].z, wc[i].w);
                    #pragma unroll
                    for (int bb = 0; bb < 2; ++bb) {
                        const u64 xx = pack2(xv[bb][i]);
                        fma2(acc[bb][0], xx, wlo);
                        fma2(acc[bb][1], xx, whi);
                    }
                }
                #pragma unroll
                for (int bb = 0; bb < 2; ++bb) {
                    const int b = bp * 2 + bb;
                    const float2 f0 = unpack2(acc[bb][0]);
                    const float2 f1 = unpack2(acc[bb][1]);
                    H4 h;
                    h.a = __floats2half2_rn(f0.x, f0.y);
                    h.b = __floats2half2_rn(f1.x, f1.y);
                    *(H4*)(p + (size_t)(b * NR + r) * PSTR + choff) = h;
                }
            }
        }
    }
    __syncthreads();

    // ======== Phase 2: routing, streamed rows, max-free softmax ========
    const int b    = t >> 7;       // 0..5  (TPB = 128)
    const int tb   = t & 127;      // 0..127
    const int wl   = tb >> 5;      // warp in group 0..3
    const int bid  = b + 1;
    const __half* pb = p + (size_t)b * NR * PSTR;
    float* sredb = sred + b * WPG * CO;
    float* wredb = wred + b * WPG;
    float* vdotb = vdot + b * CO;

    // ---- v0 = squash(mean_r p_r): one streamed pass ----
    {
        float S[CO];
        #pragma unroll
        for (int o = 0; o < CO; ++o) S[o] = 0.f;
        #pragma unroll
        for (int k = 0; k < KPT; ++k) {
            float f[CO];
            load_row_sw(pb, tb + k * TPB, f);
            #pragma unroll
            for (int o = 0; o < CO; ++o) S[o] += f[o];
        }
        reduce_s16(S, lane, sredb + wl * CO);
        bar_group(bid);
        if (tb < CO) {
            float s = 0.f;
            #pragma unroll
            for (int w = 0; w < WPG; ++w) s += sredb[w * CO + tb];
            const float v = s * (1.0f / NR);
            float sq = v * v;
            #pragma unroll
            for (int off = 8; off; off >>= 1)
                sq += __shfl_xor_sync(0xffffu, sq, off);
            const float coef = sq / ((1.f + sq) * sqrtf(sq));
            vdotb[tb] = v * coef;
        }
        bar_group(bid);
    }

    // ---- rounds 1 and 2: single fused streamed pass per round ----
    #pragma unroll
    for (int round = 0; round < 2; ++round) {
        float vd[CO];
        #pragma unroll
        for (int o = 0; o < CO; ++o) vd[o] = vdotb[o];

        float S[CO];
        #pragma unroll
        for (int o = 0; o < CO; ++o) S[o] = 0.f;
        float zloc = 0.f;

        #pragma unroll
        for (int k = 0; k < KPT; ++k) {
            float f[CO];
            load_row_sw(pb, tb + k * TPB, f);
            float a = 0.f;
            #pragma unroll
            for (int o = 0; o < CO; ++o) a += f[o] * vd[o];
            const float e = __expf(a);      // max-free: |a| <~ 20, safe
            zloc += e;
            #pragma unroll
            for (int o = 0; o < CO; ++o) S[o] += e * f[o];
        }
        #pragma unroll
        for (int off = 16; off; off >>= 1)
            zloc += __shfl_xor_sync(0xffffffffu, zloc, off);
        if (lane == 0) wredb[wl] = zloc;
        reduce_s16(S, lane, sredb + wl * CO);
        bar_group(bid);

        if (tb < CO) {
            float s = 0.f;
            #pragma unroll
            for (int w = 0; w < WPG; ++w) s += sredb[w * CO + tb];
            float Z = wredb[0];
            #pragma unroll
            for (int w = 1; w < WPG; ++w) Z += wredb[w];
            const float v = s / Z;
            float sq = v * v;
            #pragma unroll
            for (int off = 8; off; off >>= 1)
                sq += __shfl_xor_sync(0xffffu, sq, off);
            const float coef = sq / ((1.f + sq) * sqrtf(sq));
            const float res = v * coef;
            if (round == 0)
                vdotb[tb] += res;                       // w = v0 + v1
            else if (b0 + b < NB)
                out[((size_t)n * NB + (b0 + b)) * CO + tb] = res;
        }
        bar_group(bid);
    }
}

extern "C" void kernel_launch(void* const* d_in, const int* in_sizes, int n_in,
                              void* d_out, int out_size) {
    (void)in_sizes; (void)n_in; (void)out_size;
    const float* x = (const float*)d_in[0];
    const float* W = (const float*)d_in[1];
    float* out = (float*)d_out;

    const int total = NCAPS * OCT * CI * 32;
    repack_kernel<<<(total + 255) / 256, 256>>>(W);

    cudaFuncSetAttribute(caps_kernel,
                         cudaFuncAttributeMaxDynamicSharedMemorySize, SMEM_TOTAL);
    dim3 grid(GROUPS, NCAPS);
    caps_kernel<<<grid, NTHREADS, SMEM_TOTAL>>>(x, out);
}

// round 11
// speedup vs baseline: 1.6549x; 1.6549x over previous
#include <cuda_runtime.h>
#include <cuda_fp16.h>
#include <cstdint>

// CapsuleLayer dynamic routing, 3 rounds.
// x: [512, 1152, 8] fp32   W: [10, 1152, 8, 16] fp32   out: [10, 512, 16] fp32
//
// R8 structure (proven 108.6us) with ONE change: W is repacked to fp16
// (caps_Wh), halving the dominant per-block L1-crossbar term (W stream
// 576KB -> 288KB/block). Priors are already fp16; added RMS error ~2.8e-4.
//
// Pre-pass: caps_Wh[n][g][ip][rq][oq] uint4 (16B = 8 halves):
//   halves 0..3 = W[g*8+rq][2ip][4oq..4oq+3], 4..7 = same at i=2ip+1.
//   Phase-1 warp instr (fixed ip) reads 512B contiguous -> 4 wf/LDG.128.
// Phase 1: warp = row-octet; lane = (rq 0..7, oq 0..3); W converted once to
//   16 packed f32x2 regs, then b-pair split GEMM (FMA2, same order as R8).
//   Priors -> fp16 smem, PSTR=16, 8B-chunk XOR swizzle (chunk q at
//   q ^ ((r>>2)&3)): conflict-free STS.64 and LDS.64.
// Phase 2: 4 groups x 192 threads, 6 rows/thread, streamed LDS.64 rows,
//   max-free softmax (shift-invariant, |a|<~20): one fused a/e/Z/S pass per
//   round. v0 = squash(mean p). w = v0, then v0+v1 (logits additive in p).

#define NCAPS 10
#define NB    512
#define NR    1152
#define CI    8
#define CO    16
#define BT    4
#define NTHREADS 768
#define GROUPS (NB / BT)          // 128
#define TPB   192                 // threads per batch group (6 warps)
#define WPG   6
#define KPT   (NR / TPB)          // 6 rows per thread in routing
#define NWARP (NTHREADS / 32)     // 24
#define OCT   (NR / 8)            // 144 row-octets
#define JIT   (OCT / NWARP)       // 6 octets per warp
#define PSTR  16                  // halves per prior row (exact, swizzled)

// shared memory layout (bytes)
#define P_BYTES    (BT * NR * PSTR * 2)   // 147456 fp16 priors
#define SRED_OFF   P_BYTES
#define SRED_BYTES (BT * WPG * CO * 4)    // 1536
#define WRED_OFF   (SRED_OFF + SRED_BYTES)
#define WRED_BYTES (BT * WPG * 4)         // 96
#define VDOT_OFF   (WRED_OFF + WRED_BYTES)
#define VDOT_BYTES (BT * CO * 4)          // 256
#define SMEM_TOTAL (VDOT_OFF + VDOT_BYTES)

// repacked fp16 W: [NCAPS][OCT][4 ip][8 rq][4 oq] x 16B
__device__ __align__(16) uint4 caps_Wh[NCAPS * OCT * 4 * 32];

struct __align__(8) H4 { __half2 a, b; };
typedef unsigned long long u64;

__device__ __forceinline__ void fma2(u64& d, u64 a, u64 b) {
    asm("fma.rn.f32x2 %0, %1, %2, %0;" : "+l"(d) : "l"(a), "l"(b));
}
__device__ __forceinline__ u64 pack2(float x) {
    u64 r; asm("mov.b64 %0, {%1, %1};" : "=l"(r) : "f"(x)); return r;
}
__device__ __forceinline__ u64 packf2(float x, float y) {
    u64 r; asm("mov.b64 %0, {%1, %2};" : "=l"(r) : "f"(x), "f"(y)); return r;
}
__device__ __forceinline__ float2 unpack2(u64 v) {
    float2 f; asm("mov.b64 {%0, %1}, %2;" : "=f"(f.x), "=f"(f.y) : "l"(v));
    return f;
}
__device__ __forceinline__ u64 h2pk(uint32_t h) {    // half2 -> packed f32x2
    const float2 f = __half22float2(*(const __half2*)&h);
    return packf2(f.x, f.y);
}
__device__ __forceinline__ void bar_group(int id) {
    asm volatile("bar.sync %0, %1;" :: "r"(id), "r"(TPB) : "memory");
}

// Load logical row r (8B-chunk swizzled) into f[16].
__device__ __forceinline__ void load_row_sw(const __half* pb, int r,
                                            float f[CO]) {
    const uint2* base = (const uint2*)(pb + (size_t)r * PSTR);
    const int d = (r >> 2) & 3;
    #pragma unroll
    for (int q = 0; q < 4; ++q) {
        const uint2 u = base[q ^ d];
        const float2 f0 = __half22float2(*(const __half2*)&u.x);
        const float2 f1 = __half22float2(*(const __half2*)&u.y);
        f[q*4+0] = f0.x; f[q*4+1] = f0.y; f[q*4+2] = f1.x; f[q*4+3] = f1.y;
    }
}

// Split-exchange reduce of S[16] over 32 lanes: 16 shfl total.
__device__ __forceinline__ void reduce_s16(float S[CO], int lane,
                                           float* sred_warp) {
    const bool h16 = lane & 16;
    #pragma unroll
    for (int j = 0; j < 8; ++j) {
        const float snd = h16 ? S[j] : S[j + 8];
        const float kp  = h16 ? S[j + 8] : S[j];
        S[j] = kp + __shfl_xor_sync(0xffffffffu, snd, 16);
    }
    const bool h8 = lane & 8;
    #pragma unroll
    for (int j = 0; j < 4; ++j) {
        const float snd = h8 ? S[j] : S[j + 4];
        const float kp  = h8 ? S[j + 4] : S[j];
        S[j] = kp + __shfl_xor_sync(0xffffffffu, snd, 8);
    }
    const bool h4 = lane & 4;
    #pragma unroll
    for (int j = 0; j < 2; ++j) {
        const float snd = h4 ? S[j] : S[j + 2];
        const float kp  = h4 ? S[j + 2] : S[j];
        S[j] = kp + __shfl_xor_sync(0xffffffffu, snd, 4);
    }
    const bool h2 = lane & 2;
    {
        const float snd = h2 ? S[0] : S[1];
        const float kp  = h2 ? S[1] : S[0];
        S[0] = kp + __shfl_xor_sync(0xffffffffu, snd, 2);
    }
    S[0] += __shfl_xor_sync(0xffffffffu, S[0], 1);
    const int comp = ((lane >> 4) & 1) * 8 + ((lane >> 3) & 1) * 4 +
                     ((lane >> 2) & 1) * 2 + ((lane >> 1) & 1);
    if (!(lane & 1)) sred_warp[comp] = S[0];
}

// ---------- W repack (fp32 -> fp16): one thread per 16B output ----------
__global__ void __launch_bounds__(256)
repack_kernel(const float* __restrict__ W) {
    const int idx = blockIdx.x * blockDim.x + threadIdx.x;
    if (idx >= NCAPS * OCT * 4 * 32) return;
    const int oq = idx & 3;
    const int rq = (idx >> 2) & 7;
    const int ip = (idx >> 5) & 3;
    const int rb = idx >> 7;               // n*OCT + g
    const float* row = W + (size_t)(rb * 8 + rq) * 128;
    const float4 fe = *(const float4*)(row + (2*ip)     * 16 + 4*oq);
    const float4 fo = *(const float4*)(row + (2*ip + 1) * 16 + 4*oq);
    __half2 h0 = __floats2half2_rn(fe.x, fe.y);
    __half2 h1 = __floats2half2_rn(fe.z, fe.w);
    __half2 h2 = __floats2half2_rn(fo.x, fo.y);
    __half2 h3 = __floats2half2_rn(fo.z, fo.w);
    uint4 o;
    o.x = *(uint32_t*)&h0; o.y = *(uint32_t*)&h1;
    o.z = *(uint32_t*)&h2; o.w = *(uint32_t*)&h3;
    caps_Wh[idx] = o;
}

__global__ void __launch_bounds__(NTHREADS, 1)
caps_kernel(const float* __restrict__ x,
            float* __restrict__ out) {
    extern __shared__ char smem[];
    __half* p   = (__half*)smem;
    float* sred = (float*)(smem + SRED_OFF);
    float* wred = (float*)(smem + WRED_OFF);
    float* vdot = (float*)(smem + VDOT_OFF);

    const int n  = blockIdx.y;
    const int b0 = blockIdx.x * BT;
    const int t  = threadIdx.x;
    const int wid  = t >> 5;
    const int lane = t & 31;

    // ======== Phase 1: priors GEMM (octet mapping, fp16 W) ========
    // lane = (rq 0..7, oq 0..3)
    {
        const int rq = lane >> 2;
        const int oq = lane & 3;
        #pragma unroll 1
        for (int j = 0; j < JIT; ++j) {
            const int g = wid + j * NWARP;
            const int r = g * 8 + rq;
            const int d = (r >> 2) & 3;
            const int choff = (oq ^ d) << 2;          // halves within row
            // W: 4 LDG.128, each warp-instr covers 512B contiguous
            const uint4* wh =
                caps_Wh + ((size_t)(n * OCT + g) * 4) * 32 + rq * 4 + oq;
            uint4 wc4[4];
            #pragma unroll
            for (int ip = 0; ip < 4; ++ip) wc4[ip] = wh[ip * 32];
            // convert once: 16 packed f32x2 (i ascending, same order as R8)
            u64 wpk[16];
            #pragma unroll
            for (int ip = 0; ip < 4; ++ip) {
                wpk[4*ip + 0] = h2pk(wc4[ip].x);   // i=2ip,   o0 o1
                wpk[4*ip + 1] = h2pk(wc4[ip].y);   // i=2ip,   o2 o3
                wpk[4*ip + 2] = h2pk(wc4[ip].z);   // i=2ip+1, o0 o1
                wpk[4*ip + 3] = h2pk(wc4[ip].w);   // i=2ip+1, o2 o3
            }

            // b-pair split keeps live registers bounded
            #pragma unroll
            for (int bp = 0; bp < 2; ++bp) {
                float xv[2][CI];
                #pragma unroll
                for (int bb = 0; bb < 2; ++bb) {
                    const int b = bp * 2 + bb;
                    const float4* xp =
                        (const float4*)(x + ((size_t)(b0 + b) * NR + r) * CI);
                    const float4 x0 = xp[0], x1 = xp[1];
                    xv[bb][0]=x0.x; xv[bb][1]=x0.y; xv[bb][2]=x0.z; xv[bb][3]=x0.w;
                    xv[bb][4]=x1.x; xv[bb][5]=x1.y; xv[bb][6]=x1.z; xv[bb][7]=x1.w;
                }
                u64 acc[2][2];
                acc[0][0]=0ull; acc[0][1]=0ull; acc[1][0]=0ull; acc[1][1]=0ull;
                #pragma unroll
                for (int i = 0; i < CI; ++i) {
                    const u64 wlo = wpk[(i >> 1) * 4 + (i & 1) * 2 + 0];
                    const u64 whi = wpk[(i >> 1) * 4 + (i & 1) * 2 + 1];
                    #pragma unroll
                    for (int bb = 0; bb < 2; ++bb) {
                        const u64 xx = pack2(xv[bb][i]);
                        fma2(acc[bb][0], xx, wlo);
                        fma2(acc[bb][1], xx, whi);
                    }
                }
                #pragma unroll
                for (int bb = 0; bb < 2; ++bb) {
                    const int b = bp * 2 + bb;
                    const float2 f0 = unpack2(acc[bb][0]);
                    const float2 f1 = unpack2(acc[bb][1]);
                    H4 h;
                    h.a = __floats2half2_rn(f0.x, f0.y);
                    h.b = __floats2half2_rn(f1.x, f1.y);
                    *(H4*)(p + (size_t)(b * NR + r) * PSTR + choff) = h;
                }
            }
        }
    }
    __syncthreads();

    // ======== Phase 2: routing, streamed rows, max-free softmax ========
    const int b    = t / TPB;      // 0..3
    const int tb   = t % TPB;      // 0..191
    const int wl   = tb >> 5;      // warp in group 0..5
    const int bid  = b + 1;
    const __half* pb = p + (size_t)b * NR * PSTR;
    float* sredb = sred + b * WPG * CO;
    float* wredb = wred + b * WPG;
    float* vdotb = vdot + b * CO;

    // ---- v0 = squash(mean_r p_r): one streamed pass ----
    {
        float S[CO];
        #pragma unroll
        for (int o = 0; o < CO; ++o) S[o] = 0.f;
        #pragma unroll
        for (int k = 0; k < KPT; ++k) {
            float f[CO];
            load_row_sw(pb, tb + k * TPB, f);
            #pragma unroll
            for (int o = 0; o < CO; ++o) S[o] += f[o];
        }
        reduce_s16(S, lane, sredb + wl * CO);
        bar_group(bid);
        if (tb < CO) {
            float s = 0.f;
            #pragma unroll
            for (int w = 0; w < WPG; ++w) s += sredb[w * CO + tb];
            const float v = s * (1.0f / NR);
            float sq = v * v;
            #pragma unroll
            for (int off = 8; off; off >>= 1)
                sq += __shfl_xor_sync(0xffffu, sq, off);
            const float coef = sq / ((1.f + sq) * sqrtf(sq));
            vdotb[tb] = v * coef;
        }
        bar_group(bid);
    }

    // ---- rounds 1 and 2: single fused streamed pass per round ----
    #pragma unroll
    for (int round = 0; round < 2; ++round) {
        float vd[CO];
        #pragma unroll
        for (int o = 0; o < CO; ++o) vd[o] = vdotb[o];

        float S[CO];
        #pragma unroll
        for (int o = 0; o < CO; ++o) S[o] = 0.f;
        float zloc = 0.f;

        #pragma unroll
        for (int k = 0; k < KPT; ++k) {
            float f[CO];
            load_row_sw(pb, tb + k * TPB, f);
            float a = 0.f;
            #pragma unroll
            for (int o = 0; o < CO; ++o) a += f[o] * vd[o];
            const float e = __expf(a);      // max-free: |a| <~ 20, safe
            zloc += e;
            #pragma unroll
            for (int o = 0; o < CO; ++o) S[o] += e * f[o];
        }
        #pragma unroll
        for (int off = 16; off; off >>= 1)
            zloc += __shfl_xor_sync(0xffffffffu, zloc, off);
        if (lane == 0) wredb[wl] = zloc;
        reduce_s16(S, lane, sredb + wl * CO);
        bar_group(bid);

        if (tb < CO) {
            float s = 0.f;
            #pragma unroll
            for (int w = 0; w < WPG; ++w) s += sredb[w * CO + tb];
            float Z = wredb[0];
            #pragma unroll
            for (int w = 1; w < WPG; ++w) Z += wredb[w];
            const float v = s / Z;
            float sq = v * v;
            #pragma unroll
            for (int off = 8; off; off >>= 1)
                sq += __shfl_xor_sync(0xffffu, sq, off);
            const float coef = sq / ((1.f + sq) * sqrtf(sq));
            const float res = v * coef;
            if (round == 0)
                vdotb[tb] += res;                       // w = v0 + v1
            else
                out[((size_t)n * NB + (b0 + b)) * CO + tb] = res;
        }
        bar_group(bid);
    }
}

extern "C" void kernel_launch(void* const* d_in, const int* in_sizes, int n_in,
                              void* d_out, int out_size) {
    (void)in_sizes; (void)n_in; (void)out_size;
    const float* x = (const float*)d_in[0];
    const float* W = (const float*)d_in[1];
    float* out = (float*)d_out;

    const int total = NCAPS * OCT * 4 * 32;
    repack_kernel<<<(total + 255) / 256, 256>>>(W);

    cudaFuncSetAttribute(caps_kernel,
                         cudaFuncAttributeMaxDynamicSharedMemorySize, SMEM_TOTAL);
    dim3 grid(GROUPS, NCAPS);
    caps_kernel<<<grid, NTHREADS, SMEM_TOTAL>>>(x, out);
}